// round 7
// baseline (speedup 1.0000x reference)
#include <cuda_runtime.h>
#include <stdint.h>

// preds: [32, 3, 640, 640] fp32
#define B_    32
#define H_    640
#define W_    640
#define HW_   (H_ * W_)          // 409600
#define TOPK_ 1000
#define NB2   2048               // tail sort buckets
#define CAP   4096
#define TG    2.6f               // static fast-path threshold (p~0.0047 -> ~1900/img)
#define BX    100                // blocks per image
#define TPB   256
#define STAGE 1024               // per-block staging slots

typedef unsigned long long ull;

// Device scratch (zero at load; kernel restores counters each execution)
__device__ ull g_cand[B_ * CAP];
__device__ ull g_sorted[B_ * CAP];   // only used when M > 2048 (fallback path)
__device__ int g_count[B_];
__device__ int g_done[B_];

// Order-preserving bijection float -> uint (monotone increasing)
__device__ __forceinline__ unsigned int ordf(float x) {
    unsigned int u = __float_as_uint(x);
    return (u & 0x80000000u) ? ~u : (u | 0x80000000u);
}

__global__ void __launch_bounds__(TPB, 6) k_fused(const float* __restrict__ preds,
                                                  float* __restrict__ out) {
    // 32 KB aliased buffer:
    //   pass:  stage[1024] ull            -> buf[0:8K]
    //   tail:  hist[2048] u32             -> buf[0:8K]
    //          start[2048] u32            -> buf[8K:16K]
    //          keys[2048] ull (M<=2048)   -> buf[16K:32K]
    __shared__ __align__(16) unsigned char buf[32768];
    __shared__ unsigned int sh_part[TPB];
    __shared__ unsigned int sh_rmin[8], sh_rmax[8];
    __shared__ unsigned int sh_mn, sh_sh;
    __shared__ int sh_cnt, sh_base, sh_ovf, sh_flag, sh_T, sh_c2;

    const int b = blockIdx.y;
    const int t = threadIdx.x;
    const int lane = t & 31;

    // ======================= PASS PHASE =======================
    {
        ull* stage = (ull*)buf;
        if (t == 0) { sh_cnt = 0; sh_ovf = 0; }
        __syncthreads();

        const float4* __restrict__ sc = (const float4*)(preds + (size_t)b * 3 * HW_);
        const int tid = blockIdx.x * TPB + t;            // 0..25599

        float4 v[4];
#pragma unroll
        for (int j = 0; j < 4; j++) v[j] = sc[tid + j * 25600];

        unsigned int m = 0;
#pragma unroll
        for (int j = 0; j < 4; j++) {
            m |= (v[j].x >= TG) ? (1u << (4 * j + 0)) : 0u;
            m |= (v[j].y >= TG) ? (1u << (4 * j + 1)) : 0u;
            m |= (v[j].z >= TG) ? (1u << (4 * j + 2)) : 0u;
            m |= (v[j].w >= TG) ? (1u << (4 * j + 3)) : 0u;
        }

        const int nh = __popc(m);
        if (__ballot_sync(0xFFFFFFFFu, nh) != 0) {
            int pre = nh;
#pragma unroll
            for (int off = 1; off < 32; off <<= 1) {
                int x = __shfl_up_sync(0xFFFFFFFFu, pre, off);
                if (lane >= off) pre += x;
            }
            const int tot = __shfl_sync(0xFFFFFFFFu, pre, 31);
            int wbase = 0;
            if (lane == 31) wbase = atomicAdd(&sh_cnt, tot);   // shared atomic (cheap)
            wbase = __shfl_sync(0xFFFFFFFFu, wbase, 31);

            int pos = wbase + pre - nh;
            if (nh) {
#pragma unroll
                for (int j = 0; j < 4; j++) {
                    const int i4 = tid + j * 25600;
                    const float f0 = v[j].x, f1 = v[j].y, f2 = v[j].z, f3 = v[j].w;
#pragma unroll
                    for (int k = 0; k < 4; k++) {
                        if (m & (1u << (4 * j + k))) {
                            if (pos < STAGE) {
                                const float f = (k == 0) ? f0 : (k == 1) ? f1 : (k == 2) ? f2 : f3;
                                const unsigned int o = ordf(f);
                                const unsigned int idx = (unsigned int)(i4 * 4 + k);
                                stage[pos] = ((ull)o << 32) | (ull)(0xFFFFFFFFu - idx);
                            } else {
                                sh_ovf = 1;
                            }
                            pos++;
                        }
                    }
                }
            }
        }
        __syncthreads();

        // ONE global atomic per block; poison count on stage overflow
        if (t == 0) {
            int add = sh_cnt + (sh_ovf ? 1000000 : 0);
            sh_base = add ? atomicAdd(&g_count[b], add) : 0;
        }
        __syncthreads();

        const int cnt = min(sh_cnt, STAGE);
        const int base = sh_base;
        for (int i = t; i < cnt; i += TPB) {
            const int p = base + i;
            if (p < CAP) g_cand[b * CAP + p] = stage[i];
        }
    }

    // ============== DONE-COUNTER: last block per image selects ==============
    __threadfence();
    __syncthreads();
    if (t == 0) {
        const int old = atomicAdd(&g_done[b], 1);
        sh_flag = (old == BX - 1);
    }
    __syncthreads();
    if (!sh_flag) return;
    __threadfence();

    unsigned int* hist  = (unsigned int*)buf;            // 8 KB
    unsigned int* start = (unsigned int*)(buf + 8192);   // 8 KB
    ull*          skeys = (ull*)(buf + 16384);           // 16 KB (2048 keys)

    int M = g_count[b];

    // ============ FALLBACK (never taken for valid fast path) ============
    if (M < TOPK_ || M > CAP) {
        for (int i = t; i < NB2; i += TPB) hist[i] = 0u;
        if (t == 0) { sh_T = 0; sh_c2 = 0; }
        __syncthreads();

        const float4* sc = (const float4*)(preds + (size_t)b * 3 * HW_);
        for (int i = t; i < HW_ / 4; i += TPB) {
            const float4 w = sc[i];
            atomicAdd(&hist[ordf(w.x) >> 21], 1u);
            atomicAdd(&hist[ordf(w.y) >> 21], 1u);
            atomicAdd(&hist[ordf(w.z) >> 21], 1u);
            atomicAdd(&hist[ordf(w.w) >> 21], 1u);
        }
        __syncthreads();

        unsigned int seg = 0;
        for (int j = 7; j >= 0; j--) seg += hist[t * 8 + j];
        sh_part[t] = seg;
        __syncthreads();
        for (int off = 1; off < TPB; off <<= 1) {
            unsigned int vv = (t + off < TPB) ? sh_part[t + off] : 0u;
            __syncthreads();
            sh_part[t] += vv;
            __syncthreads();
        }
        unsigned int acc = sh_part[t] - seg;
        for (int j = 7; j >= 0; j--) {
            acc += hist[t * 8 + j];
            if (acc >= (unsigned)TOPK_) { atomicMax(&sh_T, t * 8 + j); break; }
        }
        __syncthreads();
        const unsigned int T = (unsigned int)sh_T;

        for (int i = t; i < HW_ / 4; i += TPB) {
            const float4 w = sc[i];
            const float f[4] = {w.x, w.y, w.z, w.w};
#pragma unroll
            for (int k = 0; k < 4; k++) {
                const unsigned int o = ordf(f[k]);
                if ((o >> 21) >= T) {
                    const int p = atomicAdd(&sh_c2, 1);
                    if (p < CAP) {
                        const unsigned int idx = (unsigned int)(i * 4 + k);
                        g_cand[b * CAP + p] = ((ull)o << 32) | (ull)(0xFFFFFFFFu - idx);
                    }
                }
            }
        }
        __syncthreads();
        M = min(sh_c2, CAP);
    }
    M = min(M, CAP);

    // ================= COUNTING SORT (descending) =================
    // keys live in SHARED when M <= 2048 (the overwhelmingly common case);
    // otherwise fall back to global g_sorted (correct, slower).
    ull* kbuf = (M <= 2048) ? skeys : &g_sorted[b * CAP];

    unsigned int lmin = 0xFFFFFFFFu, lmax = 0u;
    for (int i = t; i < M; i += TPB) {
        const unsigned int h = (unsigned int)(g_cand[b * CAP + i] >> 32);
        lmin = min(lmin, h);
        lmax = max(lmax, h);
    }
#pragma unroll
    for (int off = 16; off > 0; off >>= 1) {
        lmin = min(lmin, __shfl_down_sync(0xFFFFFFFFu, lmin, off));
        lmax = max(lmax, __shfl_down_sync(0xFFFFFFFFu, lmax, off));
    }
    if (lane == 0) { sh_rmin[t >> 5] = lmin; sh_rmax[t >> 5] = lmax; }
    for (int i = t; i < NB2; i += TPB) hist[i] = 0u;
    __syncthreads();
    if (t == 0) {
        unsigned int mn = 0xFFFFFFFFu, mx = 0u;
#pragma unroll
        for (int i = 0; i < 8; i++) { mn = min(mn, sh_rmin[i]); mx = max(mx, sh_rmax[i]); }
        const unsigned int range = mx - mn;
        const int bits = 32 - __clz(range | 1u);
        sh_sh = (bits > 11) ? (unsigned)(bits - 11) : 0u;
        sh_mn = mn;
    }
    __syncthreads();
    const unsigned int mn = sh_mn, shf = sh_sh;

    for (int i = t; i < M; i += TPB) {
        const unsigned int h = (unsigned int)(g_cand[b * CAP + i] >> 32);
        atomicAdd(&hist[(h - mn) >> shf], 1u);
    }
    __syncthreads();

    // suffix scan: start[bk] = #elements in strictly higher buckets
    unsigned int seg = 0;
    for (int j = 7; j >= 0; j--) seg += hist[t * 8 + j];
    sh_part[t] = seg;
    __syncthreads();
    for (int off = 1; off < TPB; off <<= 1) {
        unsigned int vv = (t + off < TPB) ? sh_part[t + off] : 0u;
        __syncthreads();
        sh_part[t] += vv;
        __syncthreads();
    }
    unsigned int run = sh_part[t] - seg;
    for (int j = 7; j >= 0; j--) {
        start[t * 8 + j] = run;
        run += hist[t * 8 + j];
    }
    __syncthreads();

    for (int i = t; i < NB2; i += TPB) hist[i] = 0u;   // -> intra-bucket counters
    __syncthreads();

    // scatter (global read coalesced -> shared write)
    for (int i = t; i < M; i += TPB) {
        const ull key = g_cand[b * CAP + i];
        const unsigned int bk = ((unsigned int)(key >> 32) - mn) >> shf;
        const unsigned int p = start[bk] + atomicAdd(&hist[bk], 1u);
        kbuf[p] = key;
    }
    __syncthreads();

    // per-bucket insertion sort (descending) for buckets intersecting [0, TOPK)
    for (int bk = t; bk < NB2; bk += TPB) {
        const unsigned int c = hist[bk];
        if (c > 1u && start[bk] < (unsigned)TOPK_) {
            ull* s2 = &kbuf[start[bk]];
            for (unsigned int a = 1; a < c; a++) {
                const ull kv = s2[a];
                int p2 = (int)a - 1;
                while (p2 >= 0 && s2[p2] < kv) { s2[p2 + 1] = s2[p2]; p2--; }
                s2[p2 + 1] = kv;
            }
        }
    }
    __syncthreads();

    // ================= EMIT =================
    const float* ph = preds + (size_t)b * 3 * HW_ + HW_;
    const float* pw = ph + HW_;
    float* boxes  = out;                              // [B, K, 4]
    float* scores = out + (size_t)B_ * TOPK_ * 4;     // [B, K]
    float* keep   = scores + (size_t)B_ * TOPK_;      // [B, K]

    for (int p = t; p < TOPK_; p += TPB) {
        const ull kk = kbuf[p];
        const unsigned int o = (unsigned int)(kk >> 32);
        const unsigned int u = (o & 0x80000000u) ? (o ^ 0x80000000u) : ~o;
        const float score = __uint_as_float(u);
        const unsigned int idx = 0xFFFFFFFFu - (unsigned int)(kk & 0xFFFFFFFFull);

        const float h = fmaxf(__ldg(&ph[idx]), 1e-6f) * (float)H_;
        const float w = fmaxf(__ldg(&pw[idx]), 1e-6f) * (float)W_;
        const float cx = (float)(idx % W_);
        const float cy = (float)(idx / W_);

        float* bx = boxes + ((size_t)b * TOPK_ + p) * 4;
        bx[0] = cx - 0.5f * w;
        bx[1] = cy - 0.5f * h;
        bx[2] = cx + 0.5f * w;
        bx[3] = cy + 0.5f * h;
        scores[b * TOPK_ + p] = score;
        keep[b * TOPK_ + p]   = 1.0f;
    }

    if (t == 0) { g_count[b] = 0; g_done[b] = 0; }
}

// ---------------------------------------------------------------------------
extern "C" void kernel_launch(void* const* d_in, const int* in_sizes, int n_in,
                              void* d_out, int out_size) {
    const float* preds = (const float*)d_in[0];
    float* out = (float*)d_out;

    dim3 g(BX, B_);
    k_fused<<<g, TPB>>>(preds, out);
}

// round 8
// speedup vs baseline: 1.0755x; 1.0755x over previous
#include <cuda_runtime.h>
#include <stdint.h>

// preds: [32, 3, 640, 640] fp32
#define B_    32
#define H_    640
#define W_    640
#define HW_   (H_ * W_)          // 409600
#define TOPK_ 1000
#define NB2   2048               // tail sort buckets
#define CAP   4096
#define TG    2.6f               // static fast-path threshold (p~0.0047 -> ~1900/img)
#define BX    50                 // blocks per image
#define TPB   256
#define VEC   8                  // float4 per thread (32 floats)
#define STAGE 1024               // per-block staging slots

typedef unsigned long long ull;

// Device scratch (zero at load; kernel restores counters each execution)
__device__ ull g_cand[B_ * CAP];
__device__ ull g_sorted[B_ * CAP];
__device__ int g_count[B_];
__device__ int g_done[B_];

// Order-preserving bijection float -> uint (monotone increasing)
__device__ __forceinline__ unsigned int ordf(float x) {
    unsigned int u = __float_as_uint(x);
    return (u & 0x80000000u) ? ~u : (u | 0x80000000u);
}

__global__ void __launch_bounds__(TPB, 4) k_fused(const float* __restrict__ preds,
                                                  float* __restrict__ out) {
    // 16 KB aliased buffer:
    //   pass:  stage[1024] ull   -> buf[0:8K]
    //   tail:  hist[2048] u32    -> buf[0:8K], start[2048] u32 -> buf[8K:16K]
    __shared__ __align__(16) unsigned char buf[16384];
    __shared__ unsigned int sh_part[TPB];
    __shared__ unsigned int sh_rmin[8], sh_rmax[8];
    __shared__ unsigned int sh_mn, sh_sh;
    __shared__ int sh_cnt, sh_base, sh_ovf, sh_flag, sh_T, sh_c2;

    const int b = blockIdx.y;
    const int t = threadIdx.x;
    const int lane = t & 31;

    // ======================= PASS PHASE =======================
    {
        ull* stage = (ull*)buf;
        if (t == 0) { sh_cnt = 0; sh_ovf = 0; }
        __syncthreads();

        const float4* __restrict__ sc = (const float4*)(preds + (size_t)b * 3 * HW_);
        const int tid = blockIdx.x * TPB + t;            // 0..12799

        float4 v[VEC];
#pragma unroll
        for (int j = 0; j < VEC; j++) v[j] = sc[tid + j * 12800];

        unsigned int m = 0;
#pragma unroll
        for (int j = 0; j < VEC; j++) {
            m |= (v[j].x >= TG) ? (1u << (4 * j + 0)) : 0u;
            m |= (v[j].y >= TG) ? (1u << (4 * j + 1)) : 0u;
            m |= (v[j].z >= TG) ? (1u << (4 * j + 2)) : 0u;
            m |= (v[j].w >= TG) ? (1u << (4 * j + 3)) : 0u;
        }

        const int nh = __popc(m);
        if (__ballot_sync(0xFFFFFFFFu, nh) != 0) {
            int pre = nh;
#pragma unroll
            for (int off = 1; off < 32; off <<= 1) {
                int x = __shfl_up_sync(0xFFFFFFFFu, pre, off);
                if (lane >= off) pre += x;
            }
            const int tot = __shfl_sync(0xFFFFFFFFu, pre, 31);
            int wbase = 0;
            if (lane == 31) wbase = atomicAdd(&sh_cnt, tot);   // shared atomic
            wbase = __shfl_sync(0xFFFFFFFFu, wbase, 31);

            int pos = wbase + pre - nh;
            if (nh) {
#pragma unroll
                for (int j = 0; j < VEC; j++) {
                    const int i4 = tid + j * 12800;
                    const float f0 = v[j].x, f1 = v[j].y, f2 = v[j].z, f3 = v[j].w;
#pragma unroll
                    for (int k = 0; k < 4; k++) {
                        if (m & (1u << (4 * j + k))) {
                            if (pos < STAGE) {
                                const float f = (k == 0) ? f0 : (k == 1) ? f1 : (k == 2) ? f2 : f3;
                                const unsigned int o = ordf(f);
                                const unsigned int idx = (unsigned int)(i4 * 4 + k);
                                stage[pos] = ((ull)o << 32) | (ull)(0xFFFFFFFFu - idx);
                            } else {
                                sh_ovf = 1;
                            }
                            pos++;
                        }
                    }
                }
            }
        }
        __syncthreads();

        // ONE global atomic per block; poison count on stage overflow
        if (t == 0) {
            int add = sh_cnt + (sh_ovf ? 1000000 : 0);
            sh_base = add ? atomicAdd(&g_count[b], add) : 0;
        }
        __syncthreads();

        const int cnt = min(sh_cnt, STAGE);
        const int base = sh_base;
        for (int i = t; i < cnt; i += TPB) {
            const int p = base + i;
            if (p < CAP) g_cand[b * CAP + p] = stage[i];
        }
    }

    // ===== DONE-COUNTER (release/acquire; no per-thread threadfence) =====
    __syncthreads();   // publishes block's global writes for the release below
    if (t == 0) {
        int old;
        asm volatile("atom.acq_rel.gpu.global.add.s32 %0, [%1], 1;"
                     : "=r"(old) : "l"(&g_done[b]) : "memory");
        sh_flag = (old == BX - 1);
    }
    __syncthreads();   // last block: t0's acquire ordered before all threads' reads
    if (!sh_flag) return;

    unsigned int* hist  = (unsigned int*)buf;            // 8 KB
    unsigned int* start = (unsigned int*)(buf + 8192);   // 8 KB

    int M = g_count[b];

    // ============ FALLBACK (never taken for valid fast path) ============
    if (M < TOPK_ || M > CAP) {
        for (int i = t; i < NB2; i += TPB) hist[i] = 0u;
        if (t == 0) { sh_T = 0; sh_c2 = 0; }
        __syncthreads();

        const float4* sc = (const float4*)(preds + (size_t)b * 3 * HW_);
        for (int i = t; i < HW_ / 4; i += TPB) {
            const float4 w = sc[i];
            atomicAdd(&hist[ordf(w.x) >> 21], 1u);
            atomicAdd(&hist[ordf(w.y) >> 21], 1u);
            atomicAdd(&hist[ordf(w.z) >> 21], 1u);
            atomicAdd(&hist[ordf(w.w) >> 21], 1u);
        }
        __syncthreads();

        unsigned int seg = 0;
        for (int j = 7; j >= 0; j--) seg += hist[t * 8 + j];
        sh_part[t] = seg;
        __syncthreads();
        for (int off = 1; off < TPB; off <<= 1) {
            unsigned int vv = (t + off < TPB) ? sh_part[t + off] : 0u;
            __syncthreads();
            sh_part[t] += vv;
            __syncthreads();
        }
        unsigned int acc = sh_part[t] - seg;
        for (int j = 7; j >= 0; j--) {
            acc += hist[t * 8 + j];
            if (acc >= (unsigned)TOPK_) { atomicMax(&sh_T, t * 8 + j); break; }
        }
        __syncthreads();
        const unsigned int T = (unsigned int)sh_T;

        for (int i = t; i < HW_ / 4; i += TPB) {
            const float4 w = sc[i];
            const float f[4] = {w.x, w.y, w.z, w.w};
#pragma unroll
            for (int k = 0; k < 4; k++) {
                const unsigned int o = ordf(f[k]);
                if ((o >> 21) >= T) {
                    const int p = atomicAdd(&sh_c2, 1);
                    if (p < CAP) {
                        const unsigned int idx = (unsigned int)(i * 4 + k);
                        g_cand[b * CAP + p] = ((ull)o << 32) | (ull)(0xFFFFFFFFu - idx);
                    }
                }
            }
        }
        __syncthreads();
        M = min(sh_c2, CAP);
    }
    M = min(M, CAP);

    // ================= COUNTING SORT (descending) =================
    unsigned int lmin = 0xFFFFFFFFu, lmax = 0u;
    for (int i = t; i < M; i += TPB) {
        const unsigned int h = (unsigned int)(g_cand[b * CAP + i] >> 32);
        lmin = min(lmin, h);
        lmax = max(lmax, h);
    }
#pragma unroll
    for (int off = 16; off > 0; off >>= 1) {
        lmin = min(lmin, __shfl_down_sync(0xFFFFFFFFu, lmin, off));
        lmax = max(lmax, __shfl_down_sync(0xFFFFFFFFu, lmax, off));
    }
    if (lane == 0) { sh_rmin[t >> 5] = lmin; sh_rmax[t >> 5] = lmax; }
    for (int i = t; i < NB2; i += TPB) hist[i] = 0u;
    __syncthreads();
    if (t == 0) {
        unsigned int mn = 0xFFFFFFFFu, mx = 0u;
#pragma unroll
        for (int i = 0; i < 8; i++) { mn = min(mn, sh_rmin[i]); mx = max(mx, sh_rmax[i]); }
        const unsigned int range = mx - mn;
        const int bits = 32 - __clz(range | 1u);
        sh_sh = (bits > 11) ? (unsigned)(bits - 11) : 0u;
        sh_mn = mn;
    }
    __syncthreads();
    const unsigned int mn = sh_mn, shf = sh_sh;

    for (int i = t; i < M; i += TPB) {
        const unsigned int h = (unsigned int)(g_cand[b * CAP + i] >> 32);
        atomicAdd(&hist[(h - mn) >> shf], 1u);
    }
    __syncthreads();

    // suffix scan: start[bk] = #elements in strictly higher buckets
    unsigned int seg = 0;
    for (int j = 7; j >= 0; j--) seg += hist[t * 8 + j];
    sh_part[t] = seg;
    __syncthreads();
    for (int off = 1; off < TPB; off <<= 1) {
        unsigned int vv = (t + off < TPB) ? sh_part[t + off] : 0u;
        __syncthreads();
        sh_part[t] += vv;
        __syncthreads();
    }
    unsigned int run = sh_part[t] - seg;
    for (int j = 7; j >= 0; j--) {
        start[t * 8 + j] = run;
        run += hist[t * 8 + j];
    }
    __syncthreads();

    for (int i = t; i < NB2; i += TPB) hist[i] = 0u;   // -> intra-bucket counters
    __syncthreads();

    for (int i = t; i < M; i += TPB) {
        const ull key = g_cand[b * CAP + i];
        const unsigned int bk = ((unsigned int)(key >> 32) - mn) >> shf;
        const unsigned int p = start[bk] + atomicAdd(&hist[bk], 1u);
        g_sorted[b * CAP + p] = key;
    }
    __syncthreads();

    // per-bucket insertion sort (descending) for buckets intersecting [0, TOPK)
    for (int bk = t; bk < NB2; bk += TPB) {
        const unsigned int c = hist[bk];
        if (c > 1u && start[bk] < (unsigned)TOPK_) {
            ull* s2 = &g_sorted[b * CAP + start[bk]];
            for (unsigned int a = 1; a < c; a++) {
                const ull kv = s2[a];
                int p2 = (int)a - 1;
                while (p2 >= 0 && s2[p2] < kv) { s2[p2 + 1] = s2[p2]; p2--; }
                s2[p2 + 1] = kv;
            }
        }
    }
    __syncthreads();

    // ================= EMIT =================
    const float* ph = preds + (size_t)b * 3 * HW_ + HW_;
    const float* pw = ph + HW_;
    float* boxes  = out;                              // [B, K, 4]
    float* scores = out + (size_t)B_ * TOPK_ * 4;     // [B, K]
    float* keep   = scores + (size_t)B_ * TOPK_;      // [B, K]

    for (int p = t; p < TOPK_; p += TPB) {
        const ull kk = g_sorted[b * CAP + p];
        const unsigned int o = (unsigned int)(kk >> 32);
        const unsigned int u = (o & 0x80000000u) ? (o ^ 0x80000000u) : ~o;
        const float score = __uint_as_float(u);
        const unsigned int idx = 0xFFFFFFFFu - (unsigned int)(kk & 0xFFFFFFFFull);

        const float h = fmaxf(ph[idx], 1e-6f) * (float)H_;
        const float w = fmaxf(pw[idx], 1e-6f) * (float)W_;
        const float cx = (float)(idx % W_);
        const float cy = (float)(idx / W_);

        float* bx = boxes + ((size_t)b * TOPK_ + p) * 4;
        bx[0] = cx - 0.5f * w;
        bx[1] = cy - 0.5f * h;
        bx[2] = cx + 0.5f * w;
        bx[3] = cy + 0.5f * h;
        scores[b * TOPK_ + p] = score;
        keep[b * TOPK_ + p]   = 1.0f;
    }

    if (t == 0) { g_count[b] = 0; g_done[b] = 0; }
}

// ---------------------------------------------------------------------------
extern "C" void kernel_launch(void* const* d_in, const int* in_sizes, int n_in,
                              void* d_out, int out_size) {
    const float* preds = (const float*)d_in[0];
    float* out = (float*)d_out;

    dim3 g(BX, B_);
    k_fused<<<g, TPB>>>(preds, out);
}